// round 2
// baseline (speedup 1.0000x reference)
#include <cuda_runtime.h>
#include <math.h>

#define N_NODES 20000
#define N_EDGES 320000
#define MULCH   64

// ---------------- scratch (device globals: no allocation allowed) ----------
// __align__(16): float4 loads/stores and red.global.add.v4.f32 require 16B.
__device__ __align__(16) float g_ys [N_NODES * 64];    // [n][v]
__device__ __align__(16) float g_yv [N_NODES * 192];   // [n][d][v]   d-major!
__device__ __align__(16) float g_scs[N_NODES * 64];    // [n][v]
__device__ __align__(16) float g_scv[N_NODES * 192];   // [n][d][v]
__device__ __align__(16) float g_ns [N_NODES * 128];   // [n][u]      u in [0,128)
__device__ __align__(16) float g_nv [N_NODES * 384];   // [n][d][u]
__device__ __align__(16) float g_deg[N_NODES];

// ---------------- helpers ---------------------------------------------------
__device__ __forceinline__ void red4(float* p, float x, float y, float z, float w) {
    asm volatile("red.global.add.v4.f32 [%0], {%1,%2,%3,%4};"
                 :: "l"(p), "f"(x), "f"(y), "f"(z), "f"(w) : "memory");
}

__device__ __forceinline__ float silu(float x) {
    return x * (1.0f / (1.0f + __expf(-x)));
}

// ---------------- zero scratch ----------------------------------------------
__global__ void k_zero() {
    int i = blockIdx.x * blockDim.x + threadIdx.x;
    int stride = gridDim.x * blockDim.x;
    float4 z = make_float4(0.f, 0.f, 0.f, 0.f);
    for (int j = i; j < N_NODES * 128 / 4; j += stride) ((float4*)g_ns)[j] = z;
    for (int j = i; j < N_NODES * 384 / 4; j += stride) ((float4*)g_nv)[j] = z;
    for (int j = i; j < N_NODES; j += stride) g_deg[j] = 0.f;
}

// ---------------- K1: node input transforms ---------------------------------
// ys = xs @ w1_s * inv ; yv[d] = xv[:,:,d] @ w1_v * inv ; same for sc_*
// tile = 32 nodes / block iteration, persistent blocks.
#define K1_SMEM ((4 * 4096 + 32 * 257) * 4)
__global__ __launch_bounds__(256, 2) void k_node_in(
    const float* __restrict__ nh,
    const float* __restrict__ w1s, const float* __restrict__ w1v,
    const float* __restrict__ wscs, const float* __restrict__ wscv)
{
    extern __shared__ float sm[];
    float* sW1s = sm;
    float* sW1v = sm + 4096;
    float* sWss = sm + 8192;
    float* sWsv = sm + 12288;
    float* sX   = sm + 16384;   // [32][257]

    const int tid = threadIdx.x;
    for (int i = tid; i < 4096; i += 256) {
        sW1s[i] = w1s[i]; sW1v[i] = w1v[i];
        sWss[i] = wscs[i]; sWsv[i] = wscv[i];
    }
    const int v = tid & 63;
    const int g = tid >> 6;          // 4 groups x 8 nodes
    const float inv = 0.125f;        // 1/sqrt(64)

    for (int t = blockIdx.x; t < N_NODES / 32; t += gridDim.x) {
        __syncthreads();
        const int n0 = t * 32;
        for (int i = tid; i < 32 * 256; i += 256) {
            int n = i >> 8, c = i & 255;
            sX[n * 257 + c] = nh[(n0 + n) * 256 + c];
        }
        __syncthreads();

        // scalar channels
        {
            float a0[8], a1[8];
#pragma unroll
            for (int k = 0; k < 8; k++) { a0[k] = 0.f; a1[k] = 0.f; }
            for (int u = 0; u < 64; u++) {
                float wa = sW1s[u * 64 + v], wb = sWss[u * 64 + v];
#pragma unroll
                for (int k = 0; k < 8; k++) {
                    float x = sX[(g * 8 + k) * 257 + u];
                    a0[k] += x * wa; a1[k] += x * wb;
                }
            }
#pragma unroll
            for (int k = 0; k < 8; k++) {
                int n = n0 + g * 8 + k;
                g_ys [n * 64 + v] = a0[k] * inv;
                g_scs[n * 64 + v] = a1[k] * inv;
            }
        }
        // vector channels, per spatial dim d (xv[n,u,d] = nh[n, 64 + u*3 + d])
        for (int d = 0; d < 3; d++) {
            float a0[8], a1[8];
#pragma unroll
            for (int k = 0; k < 8; k++) { a0[k] = 0.f; a1[k] = 0.f; }
            for (int u = 0; u < 64; u++) {
                float wa = sW1v[u * 64 + v], wb = sWsv[u * 64 + v];
#pragma unroll
                for (int k = 0; k < 8; k++) {
                    float x = sX[(g * 8 + k) * 257 + 64 + u * 3 + d];
                    a0[k] += x * wa; a1[k] += x * wb;
                }
            }
#pragma unroll
            for (int k = 0; k < 8; k++) {
                int n = n0 + g * 8 + k;
                g_yv [n * 192 + d * 64 + v] = a0[k] * inv;
                g_scv[n * 192 + d * 64 + v] = a1[k] * inv;
            }
        }
    }
}

// ---------------- K2: edge MLP + tensor product + scatter -------------------
// tile = 32 edges; block persistent; weights cached in smem once per block.
#define K2_SMEM ((512 + 4096 + 16384 + 2 * (32 * 65) + 256 + 128 + 64) * 4)
__global__ __launch_bounds__(256, 2) void k_edge(
    const float* __restrict__ ea, const float* __restrict__ esh,
    const int* __restrict__ ei,
    const float* __restrict__ fw1, const float* __restrict__ fw2,
    const float* __restrict__ fw3)
{
    extern __shared__ float sm[];
    float* sW1 = sm;            // [8][64]
    float* sW2 = sm + 512;      // [64][64]
    float* sW3 = sm + 4608;     // [64][256]  (16B aligned: 4608*4 bytes)
    float* sH1 = sm + 20992;    // [32][65]
    float* sH2 = sm + 23072;    // [32][65]
    float* sEA = sm + 25152;    // [32][8]
    float* sSH = sm + 25408;    // [32][4]
    int*   sSD = (int*)(sm + 25536); // src[32], dst[32]

    const int tid = threadIdx.x;
    for (int i = tid; i < 512;   i += 256) sW1[i] = fw1[i];
    for (int i = tid; i < 4096;  i += 256) sW2[i] = fw2[i];
    for (int i = tid; i < 16384; i += 256) sW3[i] = fw3[i];

    const float invs8 = 0.35355339059327373f;  // 1/sqrt(8)
    const float inv8  = 0.125f;                // 1/sqrt(64)
    const float INV_SQRT3 = 0.5773502691896258f;

    const int vq = tid & 15;    // quad of 4 output channels
    const int gg = tid >> 4;    // 16 groups x 2 edges

    for (int t = blockIdx.x; t < N_EDGES / 32; t += gridDim.x) {
        __syncthreads();
        const int e0 = t * 32;
        sEA[tid] = ea[e0 * 8 + tid];                 // 256 floats
        if (tid < 128) sSH[tid] = esh[e0 * 4 + tid];
        if (tid < 32) {
            int s = ei[e0 + tid];
            sSD[tid]      = s;
            sSD[32 + tid] = ei[N_EDGES + e0 + tid];
            atomicAdd(&g_deg[s], 1.0f);
        }
        __syncthreads();

        // stage 1: h1 = silu(ea @ fc_w1 * invs8)
#pragma unroll
        for (int j = 0; j < 8; j++) {
            int id = tid + 256 * j;
            int e = id >> 6, v = id & 63;
            float acc = 0.f;
#pragma unroll
            for (int k = 0; k < 8; k++) acc += sEA[e * 8 + k] * sW1[k * 64 + v];
            sH1[e * 65 + v] = silu(acc * invs8);
        }
        __syncthreads();

        // stage 2: h2 = silu(h1 @ fc_w2 * inv8)
#pragma unroll
        for (int j = 0; j < 8; j++) {
            int id = tid + 256 * j;
            int e = id >> 6, v = id & 63;
            float acc = 0.f;
            for (int u = 0; u < 64; u++) acc += sH1[e * 65 + u] * sW2[u * 64 + v];
            sH2[e * 65 + v] = silu(acc * inv8);
        }
        __syncthreads();

        // stage 3: w = h2 @ fc_w3 * inv8 ; tensor product; vector red scatter
#pragma unroll
        for (int ek = 0; ek < 2; ek++) {
            const int e = gg * 2 + ek;
            float4 wA = make_float4(0,0,0,0), wB = wA, wC = wA, wD = wA;
            for (int u = 0; u < 64; u++) {
                float h = sH2[e * 65 + u];
                const float4* row = (const float4*)(sW3 + u * 256);
                float4 a = row[vq], b = row[16 + vq], c = row[32 + vq], d4 = row[48 + vq];
                wA.x += h * a.x;  wA.y += h * a.y;  wA.z += h * a.z;  wA.w += h * a.w;
                wB.x += h * b.x;  wB.y += h * b.y;  wB.z += h * b.z;  wB.w += h * b.w;
                wC.x += h * c.x;  wC.y += h * c.y;  wC.z += h * c.z;  wC.w += h * c.w;
                wD.x += h * d4.x; wD.y += h * d4.y; wD.z += h * d4.z; wD.w += h * d4.w;
            }
            wA.x *= inv8; wA.y *= inv8; wA.z *= inv8; wA.w *= inv8;
            wB.x *= inv8; wB.y *= inv8; wB.z *= inv8; wB.w *= inv8;
            wC.x *= inv8; wC.y *= inv8; wC.z *= inv8; wC.w *= inv8;
            wD.x *= inv8; wD.y *= inv8; wD.z *= inv8; wD.w *= inv8;

            const float sh0 = sSH[e * 4 + 0];
            const float s1x = sSH[e * 4 + 1];
            const float s1y = sSH[e * 4 + 2];
            const float s1z = sSH[e * 4 + 3];
            const int src = sSD[e];
            const int dst = sSD[32 + e];

            const float4 es  = *(const float4*)(g_ys + dst * 64 + vq * 4);
            const float4 ev0 = *(const float4*)(g_yv + dst * 192 +       vq * 4);
            const float4 ev1 = *(const float4*)(g_yv + dst * 192 +  64 + vq * 4);
            const float4 ev2 = *(const float4*)(g_yv + dst * 192 + 128 + vq * 4);

            // m0a = wA*es*sh0 ; m0b = wD*(ev . sh1)*INV_SQRT3
            float4 m0a, m0b, dv;
            m0a.x = wA.x * es.x * sh0; m0a.y = wA.y * es.y * sh0;
            m0a.z = wA.z * es.z * sh0; m0a.w = wA.w * es.w * sh0;
            dv.x = ev0.x * s1x + ev1.x * s1y + ev2.x * s1z;
            dv.y = ev0.y * s1x + ev1.y * s1y + ev2.y * s1z;
            dv.z = ev0.z * s1x + ev1.z * s1y + ev2.z * s1z;
            dv.w = ev0.w * s1x + ev1.w * s1y + ev2.w * s1z;
            m0b.x = wD.x * dv.x * INV_SQRT3; m0b.y = wD.y * dv.y * INV_SQRT3;
            m0b.z = wD.z * dv.z * INV_SQRT3; m0b.w = wD.w * dv.w * INV_SQRT3;

            red4(g_ns + src * 128 +      vq * 4, m0a.x, m0a.y, m0a.z, m0a.w);
            red4(g_ns + src * 128 + 64 + vq * 4, m0b.x, m0b.y, m0b.z, m0b.w);

            // m1a[d] = wB*es*sh1[d] ; m1b[d] = wC*ev[d]*sh0
            float4 be;
            be.x = wB.x * es.x; be.y = wB.y * es.y; be.z = wB.z * es.z; be.w = wB.w * es.w;
            {
                float* baseA = g_nv + src * 384;
                red4(baseA + 0 * 128 + vq * 4, be.x * s1x, be.y * s1x, be.z * s1x, be.w * s1x);
                red4(baseA + 1 * 128 + vq * 4, be.x * s1y, be.y * s1y, be.z * s1y, be.w * s1y);
                red4(baseA + 2 * 128 + vq * 4, be.x * s1z, be.y * s1z, be.z * s1z, be.w * s1z);
                red4(baseA + 0 * 128 + 64 + vq * 4, wC.x * ev0.x * sh0, wC.y * ev0.y * sh0,
                                                    wC.z * ev0.z * sh0, wC.w * ev0.w * sh0);
                red4(baseA + 1 * 128 + 64 + vq * 4, wC.x * ev1.x * sh0, wC.y * ev1.y * sh0,
                                                    wC.z * ev1.z * sh0, wC.w * ev1.w * sh0);
                red4(baseA + 2 * 128 + 64 + vq * 4, wC.x * ev2.x * sh0, wC.y * ev2.y * sh0,
                                                    wC.z * ev2.z * sh0, wC.w * ev2.w * sh0);
            }
        }
    }
}

// ---------------- K3: output GEMM + residual + RMS norm ---------------------
// tile = 16 nodes / iteration; dn folded into GEMM output.
#define K3_SMEM ((2 * 8192 + 16 * 128 + 16 * 384 + 64) * 4)
__global__ __launch_bounds__(256, 2) void k_node_out(
    const float* __restrict__ w2s, const float* __restrict__ w2v,
    const float* __restrict__ gs, const float* __restrict__ gv,
    float* __restrict__ out)
{
    extern __shared__ float sm[];
    float* sW2s = sm;            // [128][64]
    float* sW2v = sm + 8192;     // [128][64]
    float* sNs  = sm + 16384;    // [16][128]
    float* sNv  = sm + 18432;    // [16][3][128]
    float* sRed = sm + 24576;    // [8 warps][8]

    const int tid = threadIdx.x;
    for (int i = tid; i < 8192; i += 256) { sW2s[i] = w2s[i]; sW2v[i] = w2v[i]; }

    const int v = tid & 63;
    const int g = tid >> 6;     // 4 groups x 4 nodes
    const int lane = tid & 31;
    const int wid = tid >> 5;
    const float inv2 = 0.08838834764831845f;  // 1/sqrt(128)

    for (int t = blockIdx.x; t < N_NODES / 16; t += gridDim.x) {
        __syncthreads();
        const int n0 = t * 16;
        for (int i = tid; i < 2048; i += 256) {
            int n = i >> 7, u = i & 127;
            sNs[i] = g_ns[(n0 + n) * 128 + u];
        }
        for (int i = tid; i < 6144; i += 256) {
            int n = i / 384, r = i % 384;
            sNv[i] = g_nv[(n0 + n) * 384 + r];
        }
        __syncthreads();

        float os[4]; float ov[4][3];
#pragma unroll
        for (int k = 0; k < 4; k++) { os[k] = 0.f; ov[k][0] = ov[k][1] = ov[k][2] = 0.f; }
        for (int u = 0; u < 128; u++) {
            float ws = sW2s[u * 64 + v], wv = sW2v[u * 64 + v];
#pragma unroll
            for (int k = 0; k < 4; k++) {
                int n = g * 4 + k;
                os[k] += sNs[n * 128 + u] * ws;
#pragma unroll
                for (int d = 0; d < 3; d++)
                    ov[k][d] += sNv[n * 384 + d * 128 + u] * wv;
            }
        }

        float ssum[4], vsum[4];
#pragma unroll
        for (int k = 0; k < 4; k++) {
            int n = n0 + g * 4 + k;
            float dn = rsqrtf(fmaxf(g_deg[n], 1.0f));
            float o = os[k] * inv2 * dn + g_scs[n * 64 + v];
            os[k] = o;
            ssum[k] = o * o;
            float vs = 0.f;
#pragma unroll
            for (int d = 0; d < 3; d++) {
                float q = ov[k][d] * inv2 * dn + g_scv[n * 192 + d * 64 + v];
                ov[k][d] = q;
                vs += q * q;
            }
            vsum[k] = vs;
        }
#pragma unroll
        for (int off = 16; off; off >>= 1) {
#pragma unroll
            for (int k = 0; k < 4; k++) {
                ssum[k] += __shfl_xor_sync(0xffffffffu, ssum[k], off);
                vsum[k] += __shfl_xor_sync(0xffffffffu, vsum[k], off);
            }
        }
        if (lane == 0) {
#pragma unroll
            for (int k = 0; k < 4; k++) {
                sRed[wid * 8 + k]     = ssum[k];
                sRed[wid * 8 + 4 + k] = vsum[k];
            }
        }
        __syncthreads();
#pragma unroll
        for (int k = 0; k < 4; k++) {
            float S  = sRed[(2 * g) * 8 + k]     + sRed[(2 * g + 1) * 8 + k];
            float Vv = sRed[(2 * g) * 8 + 4 + k] + sRed[(2 * g + 1) * 8 + 4 + k];
            float rs = rsqrtf(S  * (1.0f / 64.0f)  + 1e-5f);
            float rv = rsqrtf(Vv * (1.0f / 192.0f) + 1e-5f);
            int n = n0 + g * 4 + k;
            out[n * 256 + v] = os[k] * rs * gs[v];
            float gvv = gv[v] * rv;
#pragma unroll
            for (int d = 0; d < 3; d++)
                out[n * 256 + 64 + v * 3 + d] = ov[k][d] * gvv;
        }
    }
}

// ---------------- launcher ---------------------------------------------------
extern "C" void kernel_launch(void* const* d_in, const int* in_sizes, int n_in,
                              void* d_out, int out_size)
{
    const float* nh   = (const float*)d_in[0];
    const float* ea   = (const float*)d_in[1];
    const float* esh  = (const float*)d_in[2];
    const float* w1s  = (const float*)d_in[3];
    const float* w1v  = (const float*)d_in[4];
    const float* wscs = (const float*)d_in[5];
    const float* wscv = (const float*)d_in[6];
    const float* w2s  = (const float*)d_in[7];
    const float* w2v  = (const float*)d_in[8];
    const float* fw1  = (const float*)d_in[9];
    const float* fw2  = (const float*)d_in[10];
    const float* fw3  = (const float*)d_in[11];
    const float* gs   = (const float*)d_in[12];
    const float* gv   = (const float*)d_in[13];
    const int*   eidx = (const int*)d_in[14];
    float* out = (float*)d_out;

    cudaFuncSetAttribute(k_node_in,  cudaFuncAttributeMaxDynamicSharedMemorySize, K1_SMEM);
    cudaFuncSetAttribute(k_edge,     cudaFuncAttributeMaxDynamicSharedMemorySize, K2_SMEM);
    cudaFuncSetAttribute(k_node_out, cudaFuncAttributeMaxDynamicSharedMemorySize, K3_SMEM);

    k_zero<<<1024, 256>>>();
    k_node_in<<<296, 256, K1_SMEM>>>(nh, w1s, w1v, wscs, wscv);
    k_edge<<<296, 256, K2_SMEM>>>(ea, esh, eidx, fw1, fw2, fw3);
    k_node_out<<<296, 256, K3_SMEM>>>(w2s, w2v, gs, gv, out);
}

// round 3
// speedup vs baseline: 1.3579x; 1.3579x over previous
#include <cuda_runtime.h>
#include <math.h>

#define N_NODES 20000
#define N_EDGES 320000

// ---------------- scratch (device globals: no allocation allowed) ----------
__device__ __align__(16) float g_ys [N_NODES * 64];    // [n][v]
__device__ __align__(16) float g_yv [N_NODES * 192];   // [n][d][v]   d-major
__device__ __align__(16) float g_scs[N_NODES * 64];    // [n][v]
__device__ __align__(16) float g_scv[N_NODES * 192];   // [n][d][v]
__device__ __align__(16) float g_ns [N_NODES * 128];   // [n][u]
__device__ __align__(16) float g_nv [N_NODES * 384];   // [n][d][u]
__device__ __align__(16) float g_deg[N_NODES];

// ---------------- helpers ---------------------------------------------------
__device__ __forceinline__ void red4(float* p, float x, float y, float z, float w) {
    asm volatile("red.global.add.v4.f32 [%0], {%1,%2,%3,%4};"
                 :: "l"(p), "f"(x), "f"(y), "f"(z), "f"(w) : "memory");
}
__device__ __forceinline__ float silu(float x) {
    return x * (1.0f / (1.0f + __expf(-x)));
}

// ---------------- zero scratch ----------------------------------------------
__global__ void k_zero() {
    int i = blockIdx.x * blockDim.x + threadIdx.x;
    int stride = gridDim.x * blockDim.x;
    float4 z = make_float4(0.f, 0.f, 0.f, 0.f);
    for (int j = i; j < N_NODES * 128 / 4; j += stride) ((float4*)g_ns)[j] = z;
    for (int j = i; j < N_NODES * 384 / 4; j += stride) ((float4*)g_nv)[j] = z;
    for (int j = i; j < N_NODES; j += stride) g_deg[j] = 0.f;
}

// ---------------- K1: node input transforms (unchanged) ---------------------
#define K1_SMEM ((4 * 4096 + 32 * 257) * 4)
__global__ __launch_bounds__(256, 2) void k_node_in(
    const float* __restrict__ nh,
    const float* __restrict__ w1s, const float* __restrict__ w1v,
    const float* __restrict__ wscs, const float* __restrict__ wscv)
{
    extern __shared__ float sm[];
    float* sW1s = sm;
    float* sW1v = sm + 4096;
    float* sWss = sm + 8192;
    float* sWsv = sm + 12288;
    float* sX   = sm + 16384;   // [32][257]

    const int tid = threadIdx.x;
    for (int i = tid; i < 4096; i += 256) {
        sW1s[i] = w1s[i]; sW1v[i] = w1v[i];
        sWss[i] = wscs[i]; sWsv[i] = wscv[i];
    }
    const int v = tid & 63;
    const int g = tid >> 6;
    const float inv = 0.125f;

    for (int t = blockIdx.x; t < N_NODES / 32; t += gridDim.x) {
        __syncthreads();
        const int n0 = t * 32;
        for (int i = tid; i < 32 * 256; i += 256) {
            int n = i >> 8, c = i & 255;
            sX[n * 257 + c] = nh[(n0 + n) * 256 + c];
        }
        __syncthreads();
        {
            float a0[8], a1[8];
#pragma unroll
            for (int k = 0; k < 8; k++) { a0[k] = 0.f; a1[k] = 0.f; }
            for (int u = 0; u < 64; u++) {
                float wa = sW1s[u * 64 + v], wb = sWss[u * 64 + v];
#pragma unroll
                for (int k = 0; k < 8; k++) {
                    float x = sX[(g * 8 + k) * 257 + u];
                    a0[k] += x * wa; a1[k] += x * wb;
                }
            }
#pragma unroll
            for (int k = 0; k < 8; k++) {
                int n = n0 + g * 8 + k;
                g_ys [n * 64 + v] = a0[k] * inv;
                g_scs[n * 64 + v] = a1[k] * inv;
            }
        }
        for (int d = 0; d < 3; d++) {
            float a0[8], a1[8];
#pragma unroll
            for (int k = 0; k < 8; k++) { a0[k] = 0.f; a1[k] = 0.f; }
            for (int u = 0; u < 64; u++) {
                float wa = sW1v[u * 64 + v], wb = sWsv[u * 64 + v];
#pragma unroll
                for (int k = 0; k < 8; k++) {
                    float x = sX[(g * 8 + k) * 257 + 64 + u * 3 + d];
                    a0[k] += x * wa; a1[k] += x * wb;
                }
            }
#pragma unroll
            for (int k = 0; k < 8; k++) {
                int n = n0 + g * 8 + k;
                g_yv [n * 192 + d * 64 + v] = a0[k] * inv;
                g_scv[n * 192 + d * 64 + v] = a1[k] * inv;
            }
        }
    }
}

// ---------------- K2: edge MLP + tensor product + scatter -------------------
// Tile = 64 edges, 512 threads, 1 block/SM. Register-blocked GEMM stages so
// FMA issue, not smem crossbar, is the limit.
// smem floats: W1 512 | W2 4096 | W3 16384 | H1 64*65 | H2 64*68 | EA 512 |
//              SH 256 | SD 128
#define SM_W1 0
#define SM_W2 512
#define SM_W3 4608
#define SM_H1 20992            // pitch 65
#define SM_H2 25152            // pitch 68 (16B-aligned rows for STS.128)
#define SM_EA 29504
#define SM_SH 30016
#define SM_SD 30272
#define K2_SMEM ((30272 + 128) * 4)

__global__ __launch_bounds__(512, 1) void k_edge(
    const float* __restrict__ ea, const float* __restrict__ esh,
    const int* __restrict__ ei,
    const float* __restrict__ fw1, const float* __restrict__ fw2,
    const float* __restrict__ fw3)
{
    extern __shared__ float sm[];
    float* sW1 = sm + SM_W1;
    float* sW2 = sm + SM_W2;
    float* sW3 = sm + SM_W3;
    float* sH1 = sm + SM_H1;
    float* sH2 = sm + SM_H2;
    float* sEA = sm + SM_EA;
    float* sSH = sm + SM_SH;
    int*   sSD = (int*)(sm + SM_SD);

    const int tid = threadIdx.x;
    for (int i = tid; i < 512;   i += 512) sW1[i] = fw1[i];
    for (int i = tid; i < 4096;  i += 512) sW2[i] = fw2[i];
    for (int i = tid; i < 16384; i += 512) sW3[i] = fw3[i];

    const float invs8 = 0.35355339059327373f;  // 1/sqrt(8)
    const float inv8  = 0.125f;                // 1/sqrt(64)
    const float INV_SQRT3 = 0.5773502691896258f;

    const int v64 = tid & 63;   // stage1
    const int g8  = tid >> 6;
    const int vq  = tid & 15;   // stages 2/3 + TP: quad of 4 channels
    const int g2  = tid >> 4;   // 32 groups x 2 edges

    for (int t = blockIdx.x; t < N_EDGES / 64; t += gridDim.x) {
        __syncthreads();
        const int e0 = t * 64;
        if (tid < 128) ((float4*)sEA)[tid] = ((const float4*)(ea + e0 * 8))[tid];
        if (tid < 64)  ((float4*)sSH)[tid] = ((const float4*)(esh + e0 * 4))[tid];
        if (tid < 64) {
            int s = ei[e0 + tid];
            sSD[tid]      = s;
            sSD[64 + tid] = ei[N_EDGES + e0 + tid];
            atomicAdd(&g_deg[s], 1.0f);
        }
        __syncthreads();

        // ---- stage 1: h1 = silu(ea @ W1 * invs8)   (64e x 64v, K=8) -------
#pragma unroll
        for (int j = 0; j < 8; j++) {
            int e = g8 * 8 + j;
            float acc = 0.f;
#pragma unroll
            for (int k = 0; k < 8; k++) acc += sEA[e * 8 + k] * sW1[k * 64 + v64];
            sH1[e * 65 + v64] = silu(acc * invs8);
        }
        __syncthreads();

        // ---- stage 2: h2 = silu(h1 @ W2 * inv8)    (64e x 64v, K=64) ------
        {
            const int ebase = g2 * 2;
            float4 a0 = make_float4(0,0,0,0), a1 = a0;
            for (int u = 0; u < 64; u++) {
                float h0 = sH1[ebase * 65 + u];
                float h1v = sH1[(ebase + 1) * 65 + u];
                float4 w4 = *(const float4*)(sW2 + u * 64 + vq * 4);
                a0.x += h0 * w4.x;  a0.y += h0 * w4.y;
                a0.z += h0 * w4.z;  a0.w += h0 * w4.w;
                a1.x += h1v * w4.x; a1.y += h1v * w4.y;
                a1.z += h1v * w4.z; a1.w += h1v * w4.w;
            }
            float4 o0, o1;
            o0.x = silu(a0.x * inv8); o0.y = silu(a0.y * inv8);
            o0.z = silu(a0.z * inv8); o0.w = silu(a0.w * inv8);
            o1.x = silu(a1.x * inv8); o1.y = silu(a1.y * inv8);
            o1.z = silu(a1.z * inv8); o1.w = silu(a1.w * inv8);
            *(float4*)(sH2 + ebase * 68 + vq * 4)       = o0;
            *(float4*)(sH2 + (ebase + 1) * 68 + vq * 4) = o1;
        }
        __syncthreads();

        // ---- stage 3 + TP + scatter (per thread: 2 edges x col-quads) -----
        {
            const int ebase = g2 * 2;
            float4 wA[2], wB[2], wC[2], wD[2];
#pragma unroll
            for (int j = 0; j < 2; j++) {
                wA[j] = make_float4(0,0,0,0); wB[j] = wA[j];
                wC[j] = wA[j]; wD[j] = wA[j];
            }
            for (int u = 0; u < 64; u++) {
                const float4* row = (const float4*)(sW3 + u * 256);
                float4 a = row[vq], b = row[16 + vq], c = row[32 + vq], d4 = row[48 + vq];
                float h0 = sH2[ebase * 68 + u];
                float h1v = sH2[(ebase + 1) * 68 + u];
                wA[0].x += h0 * a.x;  wA[0].y += h0 * a.y;  wA[0].z += h0 * a.z;  wA[0].w += h0 * a.w;
                wB[0].x += h0 * b.x;  wB[0].y += h0 * b.y;  wB[0].z += h0 * b.z;  wB[0].w += h0 * b.w;
                wC[0].x += h0 * c.x;  wC[0].y += h0 * c.y;  wC[0].z += h0 * c.z;  wC[0].w += h0 * c.w;
                wD[0].x += h0 * d4.x; wD[0].y += h0 * d4.y; wD[0].z += h0 * d4.z; wD[0].w += h0 * d4.w;
                wA[1].x += h1v * a.x;  wA[1].y += h1v * a.y;  wA[1].z += h1v * a.z;  wA[1].w += h1v * a.w;
                wB[1].x += h1v * b.x;  wB[1].y += h1v * b.y;  wB[1].z += h1v * b.z;  wB[1].w += h1v * b.w;
                wC[1].x += h1v * c.x;  wC[1].y += h1v * c.y;  wC[1].z += h1v * c.z;  wC[1].w += h1v * c.w;
                wD[1].x += h1v * d4.x; wD[1].y += h1v * d4.y; wD[1].z += h1v * d4.z; wD[1].w += h1v * d4.w;
            }
#pragma unroll
            for (int j = 0; j < 2; j++) {
                const int e = ebase + j;
                float4 A = wA[j], B = wB[j], C = wC[j], D = wD[j];
                A.x *= inv8; A.y *= inv8; A.z *= inv8; A.w *= inv8;
                B.x *= inv8; B.y *= inv8; B.z *= inv8; B.w *= inv8;
                C.x *= inv8; C.y *= inv8; C.z *= inv8; C.w *= inv8;
                D.x *= inv8; D.y *= inv8; D.z *= inv8; D.w *= inv8;

                const float sh0 = sSH[e * 4 + 0];
                const float s1x = sSH[e * 4 + 1];
                const float s1y = sSH[e * 4 + 2];
                const float s1z = sSH[e * 4 + 3];
                const int src = sSD[e];
                const int dst = sSD[64 + e];

                const float4 es  = *(const float4*)(g_ys + dst * 64 + vq * 4);
                const float4 ev0 = *(const float4*)(g_yv + dst * 192 +       vq * 4);
                const float4 ev1 = *(const float4*)(g_yv + dst * 192 +  64 + vq * 4);
                const float4 ev2 = *(const float4*)(g_yv + dst * 192 + 128 + vq * 4);

                float4 m0a, m0b, dv;
                m0a.x = A.x * es.x * sh0; m0a.y = A.y * es.y * sh0;
                m0a.z = A.z * es.z * sh0; m0a.w = A.w * es.w * sh0;
                dv.x = ev0.x * s1x + ev1.x * s1y + ev2.x * s1z;
                dv.y = ev0.y * s1x + ev1.y * s1y + ev2.y * s1z;
                dv.z = ev0.z * s1x + ev1.z * s1y + ev2.z * s1z;
                dv.w = ev0.w * s1x + ev1.w * s1y + ev2.w * s1z;
                m0b.x = D.x * dv.x * INV_SQRT3; m0b.y = D.y * dv.y * INV_SQRT3;
                m0b.z = D.z * dv.z * INV_SQRT3; m0b.w = D.w * dv.w * INV_SQRT3;

                red4(g_ns + src * 128 +      vq * 4, m0a.x, m0a.y, m0a.z, m0a.w);
                red4(g_ns + src * 128 + 64 + vq * 4, m0b.x, m0b.y, m0b.z, m0b.w);

                float4 be;
                be.x = B.x * es.x; be.y = B.y * es.y; be.z = B.z * es.z; be.w = B.w * es.w;
                float* baseA = g_nv + src * 384;
                red4(baseA + 0 * 128 + vq * 4, be.x * s1x, be.y * s1x, be.z * s1x, be.w * s1x);
                red4(baseA + 1 * 128 + vq * 4, be.x * s1y, be.y * s1y, be.z * s1y, be.w * s1y);
                red4(baseA + 2 * 128 + vq * 4, be.x * s1z, be.y * s1z, be.z * s1z, be.w * s1z);
                red4(baseA + 0 * 128 + 64 + vq * 4, C.x * ev0.x * sh0, C.y * ev0.y * sh0,
                                                    C.z * ev0.z * sh0, C.w * ev0.w * sh0);
                red4(baseA + 1 * 128 + 64 + vq * 4, C.x * ev1.x * sh0, C.y * ev1.y * sh0,
                                                    C.z * ev1.z * sh0, C.w * ev1.w * sh0);
                red4(baseA + 2 * 128 + 64 + vq * 4, C.x * ev2.x * sh0, C.y * ev2.y * sh0,
                                                    C.z * ev2.z * sh0, C.w * ev2.w * sh0);
            }
        }
    }
}

// ---------------- K3: output GEMM + residual + RMS norm ---------------------
// u unrolled by 4 with float4 broadcast loads -> FMA-issue bound.
#define K3_SMEM ((2 * 8192 + 16 * 128 + 16 * 384 + 64) * 4)
__global__ __launch_bounds__(256, 2) void k_node_out(
    const float* __restrict__ w2s, const float* __restrict__ w2v,
    const float* __restrict__ gs, const float* __restrict__ gv,
    float* __restrict__ out)
{
    extern __shared__ float sm[];
    float* sW2s = sm;            // [128][64]
    float* sW2v = sm + 8192;     // [128][64]
    float* sNs  = sm + 16384;    // [16][128]
    float* sNv  = sm + 18432;    // [16][3][128]
    float* sRed = sm + 24576;    // [8 warps][8]

    const int tid = threadIdx.x;
    for (int i = tid; i < 8192; i += 256) { sW2s[i] = w2s[i]; sW2v[i] = w2v[i]; }

    const int v = tid & 63;
    const int g = tid >> 6;
    const int lane = tid & 31;
    const int wid = tid >> 5;
    const float inv2 = 0.08838834764831845f;  // 1/sqrt(128)

    for (int t = blockIdx.x; t < N_NODES / 16; t += gridDim.x) {
        __syncthreads();
        const int n0 = t * 16;
        for (int i = tid; i < 512; i += 256) {
            int n = i >> 5, w = i & 31;
            ((float4*)sNs)[i] = ((const float4*)g_ns)[(n0 + n) * 32 + w];
        }
        for (int i = tid; i < 1536; i += 256) {
            int n = i / 96, r = i - n * 96;
            ((float4*)sNv)[i] = ((const float4*)g_nv)[(n0 + n) * 96 + r];
        }
        __syncthreads();

        float os[4]; float ov[4][3];
#pragma unroll
        for (int k = 0; k < 4; k++) { os[k] = 0.f; ov[k][0] = ov[k][1] = ov[k][2] = 0.f; }
        for (int u = 0; u < 128; u += 4) {
            float ws0 = sW2s[(u+0) * 64 + v], ws1 = sW2s[(u+1) * 64 + v];
            float ws2 = sW2s[(u+2) * 64 + v], ws3 = sW2s[(u+3) * 64 + v];
            float wv0 = sW2v[(u+0) * 64 + v], wv1 = sW2v[(u+1) * 64 + v];
            float wv2 = sW2v[(u+2) * 64 + v], wv3 = sW2v[(u+3) * 64 + v];
#pragma unroll
            for (int k = 0; k < 4; k++) {
                int n = g * 4 + k;
                float4 xs = *(const float4*)(sNs + n * 128 + u);
                os[k] += xs.x * ws0 + xs.y * ws1 + xs.z * ws2 + xs.w * ws3;
#pragma unroll
                for (int d = 0; d < 3; d++) {
                    float4 xv = *(const float4*)(sNv + n * 384 + d * 128 + u);
                    ov[k][d] += xv.x * wv0 + xv.y * wv1 + xv.z * wv2 + xv.w * wv3;
                }
            }
        }

        float ssum[4], vsum[4];
#pragma unroll
        for (int k = 0; k < 4; k++) {
            int n = n0 + g * 4 + k;
            float dn = rsqrtf(fmaxf(g_deg[n], 1.0f));
            float o = os[k] * inv2 * dn + g_scs[n * 64 + v];
            os[k] = o;
            ssum[k] = o * o;
            float vs = 0.f;
#pragma unroll
            for (int d = 0; d < 3; d++) {
                float q = ov[k][d] * inv2 * dn + g_scv[n * 192 + d * 64 + v];
                ov[k][d] = q;
                vs += q * q;
            }
            vsum[k] = vs;
        }
#pragma unroll
        for (int off = 16; off; off >>= 1) {
#pragma unroll
            for (int k = 0; k < 4; k++) {
                ssum[k] += __shfl_xor_sync(0xffffffffu, ssum[k], off);
                vsum[k] += __shfl_xor_sync(0xffffffffu, vsum[k], off);
            }
        }
        if (lane == 0) {
#pragma unroll
            for (int k = 0; k < 4; k++) {
                sRed[wid * 8 + k]     = ssum[k];
                sRed[wid * 8 + 4 + k] = vsum[k];
            }
        }
        __syncthreads();
#pragma unroll
        for (int k = 0; k < 4; k++) {
            float S  = sRed[(2 * g) * 8 + k]     + sRed[(2 * g + 1) * 8 + k];
            float Vv = sRed[(2 * g) * 8 + 4 + k] + sRed[(2 * g + 1) * 8 + 4 + k];
            float rs = rsqrtf(S  * (1.0f / 64.0f)  + 1e-5f);
            float rv = rsqrtf(Vv * (1.0f / 192.0f) + 1e-5f);
            int n = n0 + g * 4 + k;
            out[n * 256 + v] = os[k] * rs * gs[v];
            float gvv = gv[v] * rv;
#pragma unroll
            for (int d = 0; d < 3; d++)
                out[n * 256 + 64 + v * 3 + d] = ov[k][d] * gvv;
        }
    }
}

// ---------------- launcher ---------------------------------------------------
extern "C" void kernel_launch(void* const* d_in, const int* in_sizes, int n_in,
                              void* d_out, int out_size)
{
    const float* nh   = (const float*)d_in[0];
    const float* ea   = (const float*)d_in[1];
    const float* esh  = (const float*)d_in[2];
    const float* w1s  = (const float*)d_in[3];
    const float* w1v  = (const float*)d_in[4];
    const float* wscs = (const float*)d_in[5];
    const float* wscv = (const float*)d_in[6];
    const float* w2s  = (const float*)d_in[7];
    const float* w2v  = (const float*)d_in[8];
    const float* fw1  = (const float*)d_in[9];
    const float* fw2  = (const float*)d_in[10];
    const float* fw3  = (const float*)d_in[11];
    const float* gs   = (const float*)d_in[12];
    const float* gv   = (const float*)d_in[13];
    const int*   eidx = (const int*)d_in[14];
    float* out = (float*)d_out;

    cudaFuncSetAttribute(k_node_in,  cudaFuncAttributeMaxDynamicSharedMemorySize, K1_SMEM);
    cudaFuncSetAttribute(k_edge,     cudaFuncAttributeMaxDynamicSharedMemorySize, K2_SMEM);
    cudaFuncSetAttribute(k_node_out, cudaFuncAttributeMaxDynamicSharedMemorySize, K3_SMEM);

    k_zero<<<1024, 256>>>();
    k_node_in<<<296, 256, K1_SMEM>>>(nh, w1s, w1v, wscs, wscv);
    k_edge<<<148, 512, K2_SMEM>>>(ea, esh, eidx, fw1, fw2, fw3);
    k_node_out<<<296, 256, K3_SMEM>>>(w2s, w2v, gs, gv, out);
}

// round 4
// speedup vs baseline: 1.4348x; 1.0567x over previous
#include <cuda_runtime.h>
#include <math.h>

#define N_NODES 20000
#define N_EDGES 320000

// ---------------- scratch (device globals: no allocation allowed) ----------
__device__ __align__(16) float g_ys [N_NODES * 64];    // [n][v]
__device__ __align__(16) float g_yv [N_NODES * 192];   // [n][d][v]   d-major
__device__ __align__(16) float g_scs[N_NODES * 64];    // [n][v]
__device__ __align__(16) float g_scv[N_NODES * 192];   // [n][d][v]
__device__ __align__(16) float g_ns [N_NODES * 128];   // [n][u]
__device__ __align__(16) float g_nv [N_NODES * 384];   // [n][d][u]
__device__ __align__(16) float g_deg[N_NODES];

typedef unsigned long long ull;

// ---------------- helpers ---------------------------------------------------
__device__ __forceinline__ void red4(float* p, float x, float y, float z, float w) {
    asm volatile("red.global.add.v4.f32 [%0], {%1,%2,%3,%4};"
                 :: "l"(p), "f"(x), "f"(y), "f"(z), "f"(w) : "memory");
}
__device__ __forceinline__ float silu(float x) {
    return x * (1.0f / (1.0f + __expf(-x)));
}
// packed fp32x2 (sm_100 PTX 8.6). ptxas never auto-fuses; inline PTX only.
__device__ __forceinline__ ull ffma2(ull a, ull b, ull c) {
    ull d;
    asm("fma.rn.f32x2 %0, %1, %2, %3;" : "=l"(d) : "l"(a), "l"(b), "l"(c));
    return d;
}
__device__ __forceinline__ ull bcast2(float x) {
    ull r;
    asm("mov.b64 %0, {%1, %1};" : "=l"(r) : "f"(x));
    return r;
}
__device__ __forceinline__ void unpack2(ull p, float& x, float& y) {
    asm("mov.b64 {%0, %1}, %2;" : "=f"(x), "=f"(y) : "l"(p));
}

// ---------------- zero scratch ----------------------------------------------
__global__ void k_zero() {
    int i = blockIdx.x * blockDim.x + threadIdx.x;
    int stride = gridDim.x * blockDim.x;
    float4 z = make_float4(0.f, 0.f, 0.f, 0.f);
    for (int j = i; j < N_NODES * 128 / 4; j += stride) ((float4*)g_ns)[j] = z;
    for (int j = i; j < N_NODES * 384 / 4; j += stride) ((float4*)g_nv)[j] = z;
    for (int j = i; j < N_NODES; j += stride) g_deg[j] = 0.f;
}

// ---------------- K1: node input transforms (FFMA2) -------------------------
// thread = column-pair (vt) x 4 nodes; weights load as b64 pairs.
#define K1_SMEM ((4 * 4096 + 32 * 257) * 4)
__global__ __launch_bounds__(256, 2) void k_node_in(
    const float* __restrict__ nh,
    const float* __restrict__ w1s, const float* __restrict__ w1v,
    const float* __restrict__ wscs, const float* __restrict__ wscv)
{
    extern __shared__ float sm[];
    float* sW1s = sm;
    float* sW1v = sm + 4096;
    float* sWss = sm + 8192;
    float* sWsv = sm + 12288;
    float* sX   = sm + 16384;   // [32][257]

    const int tid = threadIdx.x;
    for (int i = tid; i < 4096; i += 256) {
        sW1s[i] = w1s[i]; sW1v[i] = w1v[i];
        sWss[i] = wscs[i]; sWsv[i] = wscv[i];
    }
    const int vt = tid & 31;         // column pair: cols (2vt, 2vt+1)
    const int g  = tid >> 5;         // 8 groups x 4 nodes
    const float inv = 0.125f;        // 1/sqrt(64)

    for (int t = blockIdx.x; t < N_NODES / 32; t += gridDim.x) {
        __syncthreads();
        const int n0 = t * 32;
        for (int i = tid; i < 32 * 256; i += 256) {
            int n = i >> 8, c = i & 255;
            sX[n * 257 + c] = nh[(n0 + n) * 256 + c];
        }
        __syncthreads();

        // scalar pass
        {
            ull ay[4], as[4];
#pragma unroll
            for (int k = 0; k < 4; k++) { ay[k] = 0ull; as[k] = 0ull; }
            for (int u = 0; u < 64; u++) {
                ull wa = *(const ull*)(sW1s + u * 64 + vt * 2);
                ull wb = *(const ull*)(sWss + u * 64 + vt * 2);
#pragma unroll
                for (int k = 0; k < 4; k++) {
                    ull xp = bcast2(sX[(g * 4 + k) * 257 + u]);
                    ay[k] = ffma2(xp, wa, ay[k]);
                    as[k] = ffma2(xp, wb, as[k]);
                }
            }
#pragma unroll
            for (int k = 0; k < 4; k++) {
                int n = n0 + g * 4 + k;
                float a, b;
                unpack2(ay[k], a, b);
                *(float2*)(g_ys + n * 64 + vt * 2) = make_float2(a * inv, b * inv);
                unpack2(as[k], a, b);
                *(float2*)(g_scs + n * 64 + vt * 2) = make_float2(a * inv, b * inv);
            }
        }
        // vector passes
        for (int d = 0; d < 3; d++) {
            ull ay[4], as[4];
#pragma unroll
            for (int k = 0; k < 4; k++) { ay[k] = 0ull; as[k] = 0ull; }
            for (int u = 0; u < 64; u++) {
                ull wa = *(const ull*)(sW1v + u * 64 + vt * 2);
                ull wb = *(const ull*)(sWsv + u * 64 + vt * 2);
#pragma unroll
                for (int k = 0; k < 4; k++) {
                    ull xp = bcast2(sX[(g * 4 + k) * 257 + 64 + u * 3 + d]);
                    ay[k] = ffma2(xp, wa, ay[k]);
                    as[k] = ffma2(xp, wb, as[k]);
                }
            }
#pragma unroll
            for (int k = 0; k < 4; k++) {
                int n = n0 + g * 4 + k;
                float a, b;
                unpack2(ay[k], a, b);
                *(float2*)(g_yv + n * 192 + d * 64 + vt * 2) = make_float2(a * inv, b * inv);
                unpack2(as[k], a, b);
                *(float2*)(g_scv + n * 192 + d * 64 + vt * 2) = make_float2(a * inv, b * inv);
            }
        }
    }
}

// ---------------- K2: edge MLP + tensor product + scatter -------------------
// 64-edge tiles, 512 threads, 1 block/SM. FFMA2 packed over column pairs;
// node gathers prefetched at tile start so stage-3 TP never stalls on them.
#define SM_W1 0
#define SM_W2 512
#define SM_W3 4608
#define SM_H1 20992            // pitch 65
#define SM_H2 25152            // pitch 68 (16B rows)
#define SM_EA 29504
#define SM_SH 30016
#define SM_SD 30272
#define K2_SMEM ((30272 + 128) * 4)

__global__ __launch_bounds__(512, 1) void k_edge(
    const float* __restrict__ ea, const float* __restrict__ esh,
    const int* __restrict__ ei,
    const float* __restrict__ fw1, const float* __restrict__ fw2,
    const float* __restrict__ fw3)
{
    extern __shared__ float sm[];
    float* sW1 = sm + SM_W1;
    float* sW2 = sm + SM_W2;
    float* sW3 = sm + SM_W3;
    float* sH1 = sm + SM_H1;
    float* sH2 = sm + SM_H2;
    float* sEA = sm + SM_EA;
    float* sSH = sm + SM_SH;
    int*   sSD = (int*)(sm + SM_SD);

    const int tid = threadIdx.x;
    for (int i = tid; i < 512;   i += 512) sW1[i] = fw1[i];
    for (int i = tid; i < 4096;  i += 512) sW2[i] = fw2[i];
    for (int i = tid; i < 16384; i += 512) sW3[i] = fw3[i];

    const float invs8 = 0.35355339059327373f;  // 1/sqrt(8)
    const float inv8  = 0.125f;                // 1/sqrt(64)
    const float INV_SQRT3 = 0.5773502691896258f;

    const int v64 = tid & 63;   // stage1
    const int g8  = tid >> 6;
    const int vq  = tid & 15;   // quad of 4 channels
    const int g2  = tid >> 4;   // 32 groups x 2 edges

    for (int t = blockIdx.x; t < N_EDGES / 64; t += gridDim.x) {
        __syncthreads();
        const int e0 = t * 64;
        if (tid < 128) ((float4*)sEA)[tid] = ((const float4*)(ea + e0 * 8))[tid];
        if (tid < 64)  ((float4*)sSH)[tid] = ((const float4*)(esh + e0 * 4))[tid];
        if (tid < 64) {
            int s = ei[e0 + tid];
            sSD[tid]      = s;
            sSD[64 + tid] = ei[N_EDGES + e0 + tid];
            atomicAdd(&g_deg[s], 1.0f);
        }
        __syncthreads();

        // ---- prefetch node gathers for this thread's 2 edges (hides L2 lat)
        float4 pes[2], pev[2][3];
#pragma unroll
        for (int j = 0; j < 2; j++) {
            const int dst = sSD[64 + g2 * 2 + j];
            pes[j]    = *(const float4*)(g_ys + dst * 64 + vq * 4);
            pev[j][0] = *(const float4*)(g_yv + dst * 192 +       vq * 4);
            pev[j][1] = *(const float4*)(g_yv + dst * 192 +  64 + vq * 4);
            pev[j][2] = *(const float4*)(g_yv + dst * 192 + 128 + vq * 4);
        }

        // ---- stage 1: h1 = silu(ea @ W1 * invs8)
#pragma unroll
        for (int j = 0; j < 8; j++) {
            int e = g8 * 8 + j;
            float acc = 0.f;
#pragma unroll
            for (int k = 0; k < 8; k++) acc += sEA[e * 8 + k] * sW1[k * 64 + v64];
            sH1[e * 65 + v64] = silu(acc * invs8);
        }
        __syncthreads();

        // ---- stage 2: h2 = silu(h1 @ W2 * inv8)   (FFMA2, col pairs) ------
        {
            const int ebase = g2 * 2;
            ull a0[2] = {0ull, 0ull}, a1[2] = {0ull, 0ull};
            for (int u = 0; u < 64; u++) {
                ulonglong2 w2 = *(const ulonglong2*)(sW2 + u * 64 + vq * 4);
                ull h0 = bcast2(sH1[ebase * 65 + u]);
                ull h1 = bcast2(sH1[(ebase + 1) * 65 + u]);
                a0[0] = ffma2(h0, w2.x, a0[0]); a0[1] = ffma2(h0, w2.y, a0[1]);
                a1[0] = ffma2(h1, w2.x, a1[0]); a1[1] = ffma2(h1, w2.y, a1[1]);
            }
            float x0, x1, x2, x3;
            unpack2(a0[0], x0, x1); unpack2(a0[1], x2, x3);
            *(float4*)(sH2 + ebase * 68 + vq * 4) = make_float4(
                silu(x0 * inv8), silu(x1 * inv8), silu(x2 * inv8), silu(x3 * inv8));
            unpack2(a1[0], x0, x1); unpack2(a1[1], x2, x3);
            *(float4*)(sH2 + (ebase + 1) * 68 + vq * 4) = make_float4(
                silu(x0 * inv8), silu(x1 * inv8), silu(x2 * inv8), silu(x3 * inv8));
        }
        __syncthreads();

        // ---- stage 3 (FFMA2) + TP + scatter --------------------------------
        {
            const int ebase = g2 * 2;
            // acc layout per edge: A01 A23 B01 B23 C01 C23 D01 D23
            ull ac0[8], ac1[8];
#pragma unroll
            for (int i = 0; i < 8; i++) { ac0[i] = 0ull; ac1[i] = 0ull; }
            for (int u = 0; u < 64; u++) {
                const ulonglong2* row = (const ulonglong2*)(sW3 + u * 256);
                ulonglong2 qa = row[vq], qb = row[16 + vq], qc = row[32 + vq], qd = row[48 + vq];
                ull h0 = bcast2(sH2[ebase * 68 + u]);
                ull h1 = bcast2(sH2[(ebase + 1) * 68 + u]);
                ac0[0] = ffma2(h0, qa.x, ac0[0]); ac0[1] = ffma2(h0, qa.y, ac0[1]);
                ac0[2] = ffma2(h0, qb.x, ac0[2]); ac0[3] = ffma2(h0, qb.y, ac0[3]);
                ac0[4] = ffma2(h0, qc.x, ac0[4]); ac0[5] = ffma2(h0, qc.y, ac0[5]);
                ac0[6] = ffma2(h0, qd.x, ac0[6]); ac0[7] = ffma2(h0, qd.y, ac0[7]);
                ac1[0] = ffma2(h1, qa.x, ac1[0]); ac1[1] = ffma2(h1, qa.y, ac1[1]);
                ac1[2] = ffma2(h1, qb.x, ac1[2]); ac1[3] = ffma2(h1, qb.y, ac1[3]);
                ac1[4] = ffma2(h1, qc.x, ac1[4]); ac1[5] = ffma2(h1, qc.y, ac1[5]);
                ac1[6] = ffma2(h1, qd.x, ac1[6]); ac1[7] = ffma2(h1, qd.y, ac1[7]);
            }
#pragma unroll
            for (int j = 0; j < 2; j++) {
                const ull* ac = j ? ac1 : ac0;
                const int e = ebase + j;
                float4 A, B, C, D;
                unpack2(ac[0], A.x, A.y); unpack2(ac[1], A.z, A.w);
                unpack2(ac[2], B.x, B.y); unpack2(ac[3], B.z, B.w);
                unpack2(ac[4], C.x, C.y); unpack2(ac[5], C.z, C.w);
                unpack2(ac[6], D.x, D.y); unpack2(ac[7], D.z, D.w);
                A.x *= inv8; A.y *= inv8; A.z *= inv8; A.w *= inv8;
                B.x *= inv8; B.y *= inv8; B.z *= inv8; B.w *= inv8;
                C.x *= inv8; C.y *= inv8; C.z *= inv8; C.w *= inv8;
                D.x *= inv8; D.y *= inv8; D.z *= inv8; D.w *= inv8;

                const float sh0 = sSH[e * 4 + 0];
                const float s1x = sSH[e * 4 + 1];
                const float s1y = sSH[e * 4 + 2];
                const float s1z = sSH[e * 4 + 3];
                const int src = sSD[e];

                const float4 es  = pes[j];
                const float4 ev0 = pev[j][0];
                const float4 ev1 = pev[j][1];
                const float4 ev2 = pev[j][2];

                float4 m0a, m0b, dv;
                m0a.x = A.x * es.x * sh0; m0a.y = A.y * es.y * sh0;
                m0a.z = A.z * es.z * sh0; m0a.w = A.w * es.w * sh0;
                dv.x = ev0.x * s1x + ev1.x * s1y + ev2.x * s1z;
                dv.y = ev0.y * s1x + ev1.y * s1y + ev2.y * s1z;
                dv.z = ev0.z * s1x + ev1.z * s1y + ev2.z * s1z;
                dv.w = ev0.w * s1x + ev1.w * s1y + ev2.w * s1z;
                m0b.x = D.x * dv.x * INV_SQRT3; m0b.y = D.y * dv.y * INV_SQRT3;
                m0b.z = D.z * dv.z * INV_SQRT3; m0b.w = D.w * dv.w * INV_SQRT3;

                red4(g_ns + src * 128 +      vq * 4, m0a.x, m0a.y, m0a.z, m0a.w);
                red4(g_ns + src * 128 + 64 + vq * 4, m0b.x, m0b.y, m0b.z, m0b.w);

                float4 be;
                be.x = B.x * es.x; be.y = B.y * es.y; be.z = B.z * es.z; be.w = B.w * es.w;
                float* baseA = g_nv + src * 384;
                red4(baseA + 0 * 128 + vq * 4, be.x * s1x, be.y * s1x, be.z * s1x, be.w * s1x);
                red4(baseA + 1 * 128 + vq * 4, be.x * s1y, be.y * s1y, be.z * s1y, be.w * s1y);
                red4(baseA + 2 * 128 + vq * 4, be.x * s1z, be.y * s1z, be.z * s1z, be.w * s1z);
                red4(baseA + 0 * 128 + 64 + vq * 4, C.x * ev0.x * sh0, C.y * ev0.y * sh0,
                                                    C.z * ev0.z * sh0, C.w * ev0.w * sh0);
                red4(baseA + 1 * 128 + 64 + vq * 4, C.x * ev1.x * sh0, C.y * ev1.y * sh0,
                                                    C.z * ev1.z * sh0, C.w * ev1.w * sh0);
                red4(baseA + 2 * 128 + 64 + vq * 4, C.x * ev2.x * sh0, C.y * ev2.y * sh0,
                                                    C.z * ev2.z * sh0, C.w * ev2.w * sh0);
            }
        }
    }
}

// ---------------- K3: output GEMM + residual + RMS norm (FFMA2) -------------
// warp = 2 nodes; lane = column pair; shfl-only RMS reduction.
#define K3_SMEM ((2 * 8192 + 16 * 128 + 16 * 384) * 4)
__global__ __launch_bounds__(256, 2) void k_node_out(
    const float* __restrict__ w2s, const float* __restrict__ w2v,
    const float* __restrict__ gs, const float* __restrict__ gv,
    float* __restrict__ out)
{
    extern __shared__ float sm[];
    float* sW2s = sm;            // [128][64]
    float* sW2v = sm + 8192;     // [128][64]
    float* sNs  = sm + 16384;    // [16][128]
    float* sNv  = sm + 18432;    // [16][3][128]

    const int tid = threadIdx.x;
    for (int i = tid; i < 8192; i += 256) { sW2s[i] = w2s[i]; sW2v[i] = w2v[i]; }

    const int vt   = tid & 31;   // column pair (2vt, 2vt+1)
    const int warp = tid >> 5;   // 8 warps x 2 nodes = 16 nodes/tile
    const float inv2 = 0.08838834764831845f;  // 1/sqrt(128)

    for (int t = blockIdx.x; t < N_NODES / 16; t += gridDim.x) {
        __syncthreads();
        const int n0 = t * 16;
        for (int i = tid; i < 512; i += 256)
            ((float4*)sNs)[i] = ((const float4*)g_ns)[n0 * 32 + i];
        for (int i = tid; i < 1536; i += 256)
            ((float4*)sNv)[i] = ((const float4*)g_nv)[n0 * 96 + i];
        __syncthreads();

        ull oS[2] = {0ull, 0ull};
        ull oV[2][3] = {{0ull,0ull,0ull},{0ull,0ull,0ull}};
        for (int u = 0; u < 128; u++) {
            ull ws = *(const ull*)(sW2s + u * 64 + vt * 2);
            ull wv = *(const ull*)(sW2v + u * 64 + vt * 2);
#pragma unroll
            for (int k = 0; k < 2; k++) {
                int n = warp * 2 + k;
                ull xs = bcast2(sNs[n * 128 + u]);
                oS[k] = ffma2(xs, ws, oS[k]);
#pragma unroll
                for (int d = 0; d < 3; d++) {
                    ull xv = bcast2(sNv[n * 384 + d * 128 + u]);
                    oV[k][d] = ffma2(xv, wv, oV[k][d]);
                }
            }
        }

#pragma unroll
        for (int k = 0; k < 2; k++) {
            const int n = n0 + warp * 2 + k;
            const float dn = rsqrtf(fmaxf(g_deg[n], 1.0f)) * inv2;
            float s0, s1;
            unpack2(oS[k], s0, s1);
            float2 scs = *(const float2*)(g_scs + n * 64 + vt * 2);
            s0 = s0 * dn + scs.x;
            s1 = s1 * dn + scs.y;
            float v0[3], v1[3];
            float vsum = 0.f;
#pragma unroll
            for (int d = 0; d < 3; d++) {
                float a, b;
                unpack2(oV[k][d], a, b);
                float2 scv = *(const float2*)(g_scv + n * 192 + d * 64 + vt * 2);
                a = a * dn + scv.x;
                b = b * dn + scv.y;
                v0[d] = a; v1[d] = b;
                vsum += a * a + b * b;
            }
            float ssum = s0 * s0 + s1 * s1;
#pragma unroll
            for (int off = 16; off; off >>= 1) {
                ssum += __shfl_xor_sync(0xffffffffu, ssum, off);
                vsum += __shfl_xor_sync(0xffffffffu, vsum, off);
            }
            const float rs = rsqrtf(ssum * (1.0f / 64.0f)  + 1e-5f);
            const float rv = rsqrtf(vsum * (1.0f / 192.0f) + 1e-5f);
            *(float2*)(out + n * 256 + vt * 2) =
                make_float2(s0 * rs * gs[vt * 2], s1 * rs * gs[vt * 2 + 1]);
            const float gv0 = gv[vt * 2] * rv, gv1 = gv[vt * 2 + 1] * rv;
#pragma unroll
            for (int d = 0; d < 3; d++) {
                out[n * 256 + 64 + (vt * 2)     * 3 + d] = v0[d] * gv0;
                out[n * 256 + 64 + (vt * 2 + 1) * 3 + d] = v1[d] * gv1;
            }
        }
    }
}

// ---------------- launcher ---------------------------------------------------
extern "C" void kernel_launch(void* const* d_in, const int* in_sizes, int n_in,
                              void* d_out, int out_size)
{
    const float* nh   = (const float*)d_in[0];
    const float* ea   = (const float*)d_in[1];
    const float* esh  = (const float*)d_in[2];
    const float* w1s  = (const float*)d_in[3];
    const float* w1v  = (const float*)d_in[4];
    const float* wscs = (const float*)d_in[5];
    const float* wscv = (const float*)d_in[6];
    const float* w2s  = (const float*)d_in[7];
    const float* w2v  = (const float*)d_in[8];
    const float* fw1  = (const float*)d_in[9];
    const float* fw2  = (const float*)d_in[10];
    const float* fw3  = (const float*)d_in[11];
    const float* gs   = (const float*)d_in[12];
    const float* gv   = (const float*)d_in[13];
    const int*   eidx = (const int*)d_in[14];
    float* out = (float*)d_out;

    cudaFuncSetAttribute(k_node_in,  cudaFuncAttributeMaxDynamicSharedMemorySize, K1_SMEM);
    cudaFuncSetAttribute(k_edge,     cudaFuncAttributeMaxDynamicSharedMemorySize, K2_SMEM);
    cudaFuncSetAttribute(k_node_out, cudaFuncAttributeMaxDynamicSharedMemorySize, K3_SMEM);

    k_zero<<<1024, 256>>>();
    k_node_in<<<296, 256, K1_SMEM>>>(nh, w1s, w1v, wscs, wscv);
    k_edge<<<148, 512, K2_SMEM>>>(ea, esh, eidx, fw1, fw2, fw3);
    k_node_out<<<296, 256, K3_SMEM>>>(w2s, w2v, gs, gv, out);
}